// round 1
// baseline (speedup 1.0000x reference)
#include <cuda_runtime.h>
#include <cstdint>
#include <math.h>

#define Bz     32
#define Nn     100
#define Ff     514
#define FE     614      // 514 feats + 100 mask cols
#define ROWSE  101
#define NN2    10000
#define DIMMAX 10000
#define PB     79       // ceil(DIMMAX/128)

// ---------------- scratch (static device globals; no allocation) ----------------
__device__ int   d_order[Bz * DIMMAX];
__device__ int   d_count[Bz];
__device__ float d_Gg[Bz * 64];
__device__ float d_A[Bz * Nn * 64];
__device__ float d_C[Bz * Nn * 64];
__device__ float d_logit[Bz * DIMMAX];
__device__ float d_sig[Bz * DIMMAX];
__device__ float d_bmax[Bz];
__device__ float d_binv[Bz];

// ---------------- small helpers ----------------
__device__ __forceinline__ int read_dim(const int* p) {
    int v = *p;
    if (v < 1 || v > DIMMAX) {            // safety: tolerate float-encoded scalar
        float f = __int_as_float(v);
        v = (int)f;
    }
    if (v < 0) v = 0;
    if (v > DIMMAX) v = DIMMAX;
    return v;
}

__device__ __forceinline__ float my_tanh(float x) {
    // tanh(x) = 1 - 2/(exp(2x)+1)   (exact identity; __expf rel err ~2^-22)
    float e = __expf(2.0f * x);
    return 1.0f - __fdividef(2.0f, e + 1.0f);
}

__device__ __forceinline__ unsigned long long pack2(float a, float b) {
    unsigned long long r;
    asm("mov.b64 %0, {%1, %2};" : "=l"(r) : "f"(a), "f"(b));
    return r;
}
__device__ __forceinline__ void unpack2(unsigned long long v, float& a, float& b) {
    asm("mov.b64 {%0, %1}, %2;" : "=f"(a), "=f"(b) : "l"(v));
}
__device__ __forceinline__ void fma2(unsigned long long& c, unsigned long long a,
                                     unsigned long long b) {
    asm("fma.rn.f32x2 %0, %1, %2, %3;" : "=l"(c) : "l"(a), "l"(b), "l"(c));
}

// ---------------- kernel 1: stable-partition scan -> order/count ----------------
__global__ void scan_kernel(const float* __restrict__ emb, const int* __restrict__ dimp) {
    int b = blockIdx.x, t = threadIdx.x;
    int dim = read_dim(dimp);
    int lane = t & 31, w = t >> 5;
    __shared__ int warp_tot[32];
    __shared__ int s_carry;
    if (t == 0) s_carry = 0;
    __syncthreads();
    for (int c = 0; c < 10; ++c) {
        int idx = c * 1024 + t;
        int flag = 0;
        if (idx < NN2) {
            int i = idx / Nn, j = idx - i * Nn;
            flag = emb[(size_t)(b * ROWSE + 1 + i) * FE + Ff + j] > 0.5f;
        }
        unsigned bal = __ballot_sync(0xffffffffu, flag);
        int wpre = __popc(bal & ((1u << lane) - 1u));
        if (lane == 0) warp_tot[w] = __popc(bal);
        __syncthreads();
        int wbase = 0;
        for (int ww = 0; ww < w; ++ww) wbase += warp_tot[ww];
        int rank = s_carry + wbase + wpre;
        if (flag && rank < dim) d_order[b * DIMMAX + rank] = idx;
        __syncthreads();
        if (t == 0) {
            int tot = 0;
            for (int ww = 0; ww < 32; ++ww) tot += warp_tot[ww];
            s_carry += tot;
        }
        __syncthreads();
    }
    if (t == 0) d_count[b] = s_carry;
}

// ---------------- kernel 2: Gg[b] = g @ W0[0:514] + b0 ----------------
__global__ void g_kernel(const float* __restrict__ emb, const float* __restrict__ w0,
                         const float* __restrict__ b0) {
    __shared__ float row[516];
    int b = blockIdx.x, t = threadIdx.x;  // 64 threads
    for (int k = t; k < Ff; k += 64) row[k] = emb[(size_t)b * ROWSE * FE + k];
    __syncthreads();
    float acc = b0[t];
    for (int k = 0; k < Ff; ++k) acc += row[k] * w0[(size_t)k * 64 + t];
    d_Gg[b * 64 + t] = acc;
}

// ---------------- kernel 3: A = nodes @ W0[514:1028], C = nodes @ W0[1028:1542] ----------------
__global__ void ac_kernel(const float* __restrict__ emb, const float* __restrict__ w0) {
    __shared__ float rows[20][516];
    int gy = blockIdx.x;          // 0..4  (20 node rows each)
    int b = blockIdx.y;
    int t = threadIdx.x;          // 256
    int R0 = 1 + gy * 20;
    for (int e = t; e < 20 * Ff; e += 256) {
        int r = e / Ff, k = e - r * Ff;
        rows[r][k] = emb[(size_t)(b * ROWSE + R0 + r) * FE + k];
    }
    __syncthreads();
    int j = t & 127, half = t >> 7;
    const float* wcol = w0 + ((j < 64) ? ((size_t)Ff * 64 + j)
                                       : ((size_t)2 * Ff * 64 + (j - 64)));
    float acc[10];
#pragma unroll
    for (int rr = 0; rr < 10; ++rr) acc[rr] = 0.f;
    for (int k4 = 0; k4 < 512; k4 += 4) {
        float wv0 = wcol[(size_t)(k4 + 0) * 64];
        float wv1 = wcol[(size_t)(k4 + 1) * 64];
        float wv2 = wcol[(size_t)(k4 + 2) * 64];
        float wv3 = wcol[(size_t)(k4 + 3) * 64];
#pragma unroll
        for (int rr = 0; rr < 10; ++rr) {
            int r = half + 2 * rr;
            float4 hv = *(const float4*)&rows[r][k4];
            acc[rr] += hv.x * wv0 + hv.y * wv1 + hv.z * wv2 + hv.w * wv3;
        }
    }
    {
        float wv0 = wcol[(size_t)512 * 64], wv1 = wcol[(size_t)513 * 64];
#pragma unroll
        for (int rr = 0; rr < 10; ++rr) {
            int r = half + 2 * rr;
            acc[rr] += rows[r][512] * wv0 + rows[r][513] * wv1;
        }
    }
#pragma unroll
    for (int rr = 0; rr < 10; ++rr) {
        int node = gy * 20 + half + 2 * rr;
        if (j < 64) d_A[((size_t)(b * Nn + node)) * 64 + j] = acc[rr];
        else        d_C[((size_t)(b * Nn + node)) * 64 + (j - 64)] = acc[rr];
    }
}

// ---------------- fully-unrolled 64x64 hidden layer (f32x2 packed FMA) ----------------
__device__ __forceinline__ void layer64(float (&h)[64], const float* __restrict__ sW,
                                        const float* __restrict__ sb) {
    unsigned long long acc[32];
    const float2* b2 = (const float2*)sb;
#pragma unroll
    for (int j = 0; j < 32; ++j) {
        float2 bb = b2[j];
        acc[j] = pack2(bb.x, bb.y);
    }
    const ulonglong2* W4 = (const ulonglong2*)sW;
#pragma unroll
    for (int k = 0; k < 64; ++k) {
        unsigned long long hh = pack2(h[k], h[k]);
#pragma unroll
        for (int j2 = 0; j2 < 16; ++j2) {
            ulonglong2 w = W4[k * 16 + j2];
            fma2(acc[2 * j2 + 0], hh, w.x);
            fma2(acc[2 * j2 + 1], hh, w.y);
        }
    }
#pragma unroll
    for (int j = 0; j < 32; ++j) {
        float a, b;
        unpack2(acc[j], a, b);
        h[2 * j + 0] = my_tanh(a);
        h[2 * j + 1] = my_tanh(b);
    }
}

// ---------------- kernel 4: per-pair MLP -> logit, sigmoid ----------------
__global__ __launch_bounds__(128) void pair_kernel(
    const float* __restrict__ aw1, const float* __restrict__ ab1,
    const float* __restrict__ aw2, const float* __restrict__ ab2,
    const float* __restrict__ aw3, const float* __restrict__ ab3,
    const float* __restrict__ ab0, const int* __restrict__ dimp) {
    __shared__ __align__(16) float sW1[4096];
    __shared__ __align__(16) float sW2[4096];
    __shared__ __align__(16) float sW3[128];
    __shared__ float sb1[64], sb2[64], sb3[2], sGg[64], sb0[64];
    int dim = read_dim(dimp);
    int p0 = blockIdx.x * 128;
    if (p0 >= dim) return;               // uniform block exit
    int b = blockIdx.y, t = threadIdx.x;
    for (int i = t; i < 4096; i += 128) {
        sW1[i] = aw1[i];
        sW2[i] = aw2[i];
    }
    if (t < 64) {
        sb1[t] = ab1[t];
        sb2[t] = ab2[t];
        sGg[t] = d_Gg[b * 64 + t];
        sb0[t] = ab0[t];
        sW3[2 * t + 0] = aw3[2 * t + 0];
        sW3[2 * t + 1] = aw3[2 * t + 1];
    }
    if (t < 2) sb3[t] = ab3[t];
    __syncthreads();
    int p = p0 + t;
    if (p >= dim) return;                // no further barriers below
    int cnt = d_count[b];
    float h[64];
    if (p < cnt) {
        int q = d_order[b * DIMMAX + p];
        int i1 = q / Nn, i2 = q - i1 * Nn;
        const float4* Ga = (const float4*)(d_A + ((size_t)(b * Nn + i1)) * 64);
        const float4* Cc = (const float4*)(d_C + ((size_t)(b * Nn + i2)) * 64);
#pragma unroll
        for (int kk = 0; kk < 16; ++kk) {
            float4 a = Ga[kk], c = Cc[kk];
            h[4 * kk + 0] = my_tanh(sGg[4 * kk + 0] + a.x + c.x);
            h[4 * kk + 1] = my_tanh(sGg[4 * kk + 1] + a.y + c.y);
            h[4 * kk + 2] = my_tanh(sGg[4 * kk + 2] + a.z + c.z);
            h[4 * kk + 3] = my_tanh(sGg[4 * kk + 3] + a.w + c.w);
        }
    } else {
        // invalid pair: input was zeroed -> pre-activation is just b0
#pragma unroll
        for (int k = 0; k < 64; ++k) h[k] = my_tanh(sb0[k]);
    }
    layer64(h, sW1, sb1);
    layer64(h, sW2, sb2);
    float lg = sb3[0], bl = sb3[1];
#pragma unroll
    for (int k = 0; k < 64; ++k) {
        float2 w = ((const float2*)sW3)[k];
        lg += h[k] * w.x;
        bl += h[k] * w.y;
    }
    d_logit[b * DIMMAX + p] = lg;
    d_sig[b * DIMMAX + p] = 1.0f / (1.0f + __expf(-bl));
}

// ---------------- kernel 5: per-batch softmax stats ----------------
__global__ void softmax_kernel(const int* __restrict__ dimp) {
    int b = blockIdx.x, t = threadIdx.x;  // 512 threads
    int dim = read_dim(dimp);
    __shared__ float red[16];
    __shared__ float sM;
    float m = -3.0e38f;
    for (int p = t; p < dim; p += 512) m = fmaxf(m, d_logit[b * DIMMAX + p]);
#pragma unroll
    for (int o = 16; o; o >>= 1) m = fmaxf(m, __shfl_xor_sync(0xffffffffu, m, o));
    if ((t & 31) == 0) red[t >> 5] = m;
    __syncthreads();
    if (t == 0) {
        float mm = red[0];
        for (int i = 1; i < 16; ++i) mm = fmaxf(mm, red[i]);
        sM = mm;
    }
    __syncthreads();
    m = sM;
    float s = 0.f;
    for (int p = t; p < dim; p += 512) s += __expf(d_logit[b * DIMMAX + p] - m);
#pragma unroll
    for (int o = 16; o; o >>= 1) s += __shfl_xor_sync(0xffffffffu, s, o);
    if ((t & 31) == 0) red[t >> 5] = s;
    __syncthreads();
    if (t == 0) {
        float tot = 0.f;
        for (int i = 0; i < 16; ++i) tot += red[i];
        d_bmax[b] = m;
        d_binv[b] = 1.0f / tot;
    }
}

// ---------------- kernel 6: scatter pi / pi_wb into output ----------------
__global__ void scatter_kernel(float* __restrict__ out, const int* __restrict__ dimp) {
    int dim = read_dim(dimp);
    int p = blockIdx.x * 128 + threadIdx.x;
    int b = blockIdx.y;
    if (p >= dim) return;
    if (p >= d_count[b]) return;  // valid == 0 -> contributes zeros only
    int q = d_order[b * DIMMAX + p];
    float pi = __expf(d_logit[b * DIMMAX + p] - d_bmax[b]) * d_binv[b];
    float s = d_sig[b * DIMMAX + p];
    float* ob = out + (size_t)b * 20000;
    ob[q] = pi * s;
    ob[10000 + q] = pi * (1.0f - s);
}

// ---------------- kernel 7: critic value head ----------------
__global__ void critic_kernel(const float* __restrict__ emb,
                              const float* __restrict__ cw0, const float* __restrict__ cb0,
                              const float* __restrict__ cw1, const float* __restrict__ cb1,
                              const float* __restrict__ cw2, const float* __restrict__ cb2,
                              const float* __restrict__ cw3, const float* __restrict__ cb3,
                              float* __restrict__ out, int voff) {
    __shared__ float row[516];
    __shared__ float ha[64];
    __shared__ float hb[64];
    int b = blockIdx.x, t = threadIdx.x;  // 64 threads
    for (int k = t; k < Ff; k += 64) row[k] = emb[(size_t)b * ROWSE * FE + k];
    __syncthreads();
    float acc = cb0[t];
    for (int k = 0; k < Ff; ++k) acc += row[k] * cw0[(size_t)k * 64 + t];
    ha[t] = my_tanh(acc);
    __syncthreads();
    acc = cb1[t];
    for (int k = 0; k < 64; ++k) acc += ha[k] * cw1[k * 64 + t];
    hb[t] = my_tanh(acc);
    __syncthreads();
    acc = cb2[t];
    for (int k = 0; k < 64; ++k) acc += hb[k] * cw2[k * 64 + t];
    ha[t] = my_tanh(acc);
    __syncthreads();
    if (t == 0) {
        float v = cb3[0];
        for (int k = 0; k < 64; ++k) v += ha[k] * cw3[k];
        out[voff + b] = v;
    }
}

// ---------------- launcher ----------------
extern "C" void kernel_launch(void* const* d_in, const int* in_sizes, int n_in,
                              void* d_out, int out_size) {
    const float* emb = (const float*)d_in[0];
    const int* dimp;
    int base;
    if (n_in >= 18 && in_sizes[1] == 1) {   // dict order: emb, dim, actor..., critic...
        dimp = (const int*)d_in[1];
        base = 2;
    } else {                                // signature order: emb, actor..., critic..., dim
        dimp = (const int*)d_in[n_in - 1];
        base = 1;
    }
    const float* aw0 = (const float*)d_in[base + 0];
    const float* ab0 = (const float*)d_in[base + 1];
    const float* aw1 = (const float*)d_in[base + 2];
    const float* ab1 = (const float*)d_in[base + 3];
    const float* aw2 = (const float*)d_in[base + 4];
    const float* ab2 = (const float*)d_in[base + 5];
    const float* aw3 = (const float*)d_in[base + 6];
    const float* ab3 = (const float*)d_in[base + 7];
    const float* cw0 = (const float*)d_in[base + 8];
    const float* cb0 = (const float*)d_in[base + 9];
    const float* cw1 = (const float*)d_in[base + 10];
    const float* cb1 = (const float*)d_in[base + 11];
    const float* cw2 = (const float*)d_in[base + 12];
    const float* cb2 = (const float*)d_in[base + 13];
    const float* cw3 = (const float*)d_in[base + 14];
    const float* cb3 = (const float*)d_in[base + 15];

    float* out = (float*)d_out;
    int voff = out_size - Bz;  // value slot after the filled region (expect 640000)

    cudaMemsetAsync(d_out, 0, (size_t)out_size * sizeof(float), 0);
    scan_kernel<<<Bz, 1024>>>(emb, dimp);
    g_kernel<<<Bz, 64>>>(emb, aw0, ab0);
    ac_kernel<<<dim3(5, Bz), 256>>>(emb, aw0);
    pair_kernel<<<dim3(PB, Bz), 128>>>(aw1, ab1, aw2, ab2, aw3, ab3, ab0, dimp);
    softmax_kernel<<<Bz, 512>>>(dimp);
    scatter_kernel<<<dim3(PB, Bz), 128>>>(out, dimp);
    critic_kernel<<<Bz, 64>>>(emb, cw0, cb0, cw1, cb1, cw2, cb2, cw3, cb3, out, voff);
}

// round 2
// speedup vs baseline: 1.2106x; 1.2106x over previous
#include <cuda_runtime.h>
#include <cstdint>
#include <math.h>

#define Bz     32
#define Nn     100
#define Ff     514
#define FE     614      // 514 feats + 100 mask cols
#define ROWSE  101
#define NN2    10000
#define DIMMAX 10000
#define BLKP   128      // pairs per block in pair kernel
#define PBLK   79       // ceil(DIMMAX/128)

// ---------------- scratch (static device globals; no allocation) ----------------
__device__ int   d_order[Bz * DIMMAX];
__device__ int   d_count[Bz];
__device__ float d_Gg[Bz * 64];
__device__ float d_A[Bz * Nn * 64];
__device__ float d_C[Bz * Nn * 64];
__device__ float d_logit[Bz * DIMMAX];
__device__ float d_sig[Bz * DIMMAX];
__device__ float d_bmax[Bz];
__device__ float d_binv[Bz];

// ---------------- small helpers ----------------
__device__ __forceinline__ int read_dim(const int* p) {
    int v = *p;
    if (v < 1 || v > DIMMAX) {            // safety: tolerate float-encoded scalar
        float f = __int_as_float(v);
        v = (int)f;
    }
    if (v < 0) v = 0;
    if (v > DIMMAX) v = DIMMAX;
    return v;
}

__device__ __forceinline__ float my_tanh(float x) {
    // tanh(x) = 1 - 2/(exp(2x)+1)   (exact identity; __expf rel err ~2^-22)
    float e = __expf(2.0f * x);
    return 1.0f - __fdividef(2.0f, e + 1.0f);
}

// ---------------- kernel 1: stable-partition scan -> order/count ----------------
__global__ void scan_kernel(const float* __restrict__ emb, const int* __restrict__ dimp) {
    int b = blockIdx.x, t = threadIdx.x;
    int dim = read_dim(dimp);
    int lane = t & 31, w = t >> 5;
    __shared__ int warp_tot[32];
    __shared__ int s_carry;
    if (t == 0) s_carry = 0;
    __syncthreads();
    for (int c = 0; c < 10; ++c) {
        int idx = c * 1024 + t;
        int flag = 0;
        if (idx < NN2) {
            int i = idx / Nn, j = idx - i * Nn;
            flag = emb[(size_t)(b * ROWSE + 1 + i) * FE + Ff + j] > 0.5f;
        }
        unsigned bal = __ballot_sync(0xffffffffu, flag);
        int wpre = __popc(bal & ((1u << lane) - 1u));
        if (lane == 0) warp_tot[w] = __popc(bal);
        __syncthreads();
        int wbase = 0;
        for (int ww = 0; ww < w; ++ww) wbase += warp_tot[ww];
        int rank = s_carry + wbase + wpre;
        if (flag && rank < dim) d_order[b * DIMMAX + rank] = idx;
        __syncthreads();
        if (t == 0) {
            int tot = 0;
            for (int ww = 0; ww < 32; ++ww) tot += warp_tot[ww];
            s_carry += tot;
        }
        __syncthreads();
    }
    if (t == 0) d_count[b] = s_carry;
}

// ---------------- kernel 2: Gg[b] = g @ W0[0:514] + b0 ----------------
__global__ void g_kernel(const float* __restrict__ emb, const float* __restrict__ w0,
                         const float* __restrict__ b0) {
    __shared__ float row[516];
    int b = blockIdx.x, t = threadIdx.x;  // 64 threads
    for (int k = t; k < Ff; k += 64) row[k] = emb[(size_t)b * ROWSE * FE + k];
    __syncthreads();
    float acc = b0[t];
    for (int k = 0; k < Ff; ++k) acc += row[k] * w0[(size_t)k * 64 + t];
    d_Gg[b * 64 + t] = acc;
}

// ---------------- kernel 3: A = nodes @ W0[514:1028], C = nodes @ W0[1028:1542] ----------------
__global__ void ac_kernel(const float* __restrict__ emb, const float* __restrict__ w0) {
    __shared__ float rows[20][516];
    int gy = blockIdx.x;          // 0..4  (20 node rows each)
    int b = blockIdx.y;
    int t = threadIdx.x;          // 256
    int R0 = 1 + gy * 20;
    for (int e = t; e < 20 * Ff; e += 256) {
        int r = e / Ff, k = e - r * Ff;
        rows[r][k] = emb[(size_t)(b * ROWSE + R0 + r) * FE + k];
    }
    __syncthreads();
    int j = t & 127, half = t >> 7;
    const float* wcol = w0 + ((j < 64) ? ((size_t)Ff * 64 + j)
                                       : ((size_t)2 * Ff * 64 + (j - 64)));
    float acc[10];
#pragma unroll
    for (int rr = 0; rr < 10; ++rr) acc[rr] = 0.f;
    for (int k4 = 0; k4 < 512; k4 += 4) {
        float wv0 = wcol[(size_t)(k4 + 0) * 64];
        float wv1 = wcol[(size_t)(k4 + 1) * 64];
        float wv2 = wcol[(size_t)(k4 + 2) * 64];
        float wv3 = wcol[(size_t)(k4 + 3) * 64];
#pragma unroll
        for (int rr = 0; rr < 10; ++rr) {
            int r = half + 2 * rr;
            float4 hv = *(const float4*)&rows[r][k4];
            acc[rr] += hv.x * wv0 + hv.y * wv1 + hv.z * wv2 + hv.w * wv3;
        }
    }
    {
        float wv0 = wcol[(size_t)512 * 64], wv1 = wcol[(size_t)513 * 64];
#pragma unroll
        for (int rr = 0; rr < 10; ++rr) {
            int r = half + 2 * rr;
            acc[rr] += rows[r][512] * wv0 + rows[r][513] * wv1;
        }
    }
#pragma unroll
    for (int rr = 0; rr < 10; ++rr) {
        int node = gy * 20 + half + 2 * rr;
        if (j < 64) d_A[((size_t)(b * Nn + node)) * 64 + j] = acc[rr];
        else        d_C[((size_t)(b * Nn + node)) * 64 + (j - 64)] = acc[rr];
    }
}

// ================= pair kernel v2: blocked SGEMM, 8x8 register tiles ============
// Shared layout (dynamic):
struct PairSmem {
    float W[2][4096];   // W1, W2 (k-major [k][j])
    float X[64 * 128];  // activations transposed [k][pair], XOR-swizzled 16B groups
    float W3[128];      // [k][2]
    float b1[64], b2[64], b0[64], Gg[64];
    float b3[2];
};
#define PAIR_SMEM_BYTES ((int)sizeof(PairSmem))

// element address in X for (row k, pair p): 16B-group XOR swizzle keyed on (k>>3)&7
__device__ __forceinline__ int xaddr(int k, int p) {
    return k * 128 + ((((p) >> 2) ^ ((k >> 3) & 7)) << 2) + (p & 3);
}

__device__ __forceinline__ void gemm64(const float* __restrict__ sX,
                                       const float* __restrict__ sW,
                                       const float* __restrict__ sb,
                                       float (&acc)[8][8], int jg, int pg) {
    // init with bias
#pragma unroll
    for (int ji = 0; ji < 8; ++ji) {
        float bj = sb[jg * 8 + ji];
#pragma unroll
        for (int pi = 0; pi < 8; ++pi) acc[ji][pi] = bj;
    }
    const float* wbase = sW + jg * 8;
    for (int k8 = 0; k8 < 8; ++k8) {
        int r = k8;  // (k>>3)&7 for k in this strip
        const float* xA = sX + k8 * 8 * 128 + (((2 * pg) ^ r) << 2);
        const float* xB = sX + k8 * 8 * 128 + (((2 * pg + 1) ^ r) << 2);
        const float* wk = wbase + k8 * 8 * 64;
#pragma unroll
        for (int kk = 0; kk < 8; ++kk) {
            float4 a0 = *(const float4*)(xA + kk * 128);
            float4 a1 = *(const float4*)(xB + kk * 128);
            float4 w0 = *(const float4*)(wk + kk * 64);
            float4 w1 = *(const float4*)(wk + kk * 64 + 4);
            float as[8] = {a0.x, a0.y, a0.z, a0.w, a1.x, a1.y, a1.z, a1.w};
            float ws[8] = {w0.x, w0.y, w0.z, w0.w, w1.x, w1.y, w1.z, w1.w};
#pragma unroll
            for (int ji = 0; ji < 8; ++ji)
#pragma unroll
                for (int pi = 0; pi < 8; ++pi)
                    acc[ji][pi] += ws[ji] * as[pi];
        }
    }
}

__device__ __forceinline__ void tanh_store(float* __restrict__ sX,
                                           float (&acc)[8][8], int jg, int pg) {
#pragma unroll
    for (int ji = 0; ji < 8; ++ji) {
        int j = jg * 8 + ji;
        float4 lo, hi;
        lo.x = my_tanh(acc[ji][0]); lo.y = my_tanh(acc[ji][1]);
        lo.z = my_tanh(acc[ji][2]); lo.w = my_tanh(acc[ji][3]);
        hi.x = my_tanh(acc[ji][4]); hi.y = my_tanh(acc[ji][5]);
        hi.z = my_tanh(acc[ji][6]); hi.w = my_tanh(acc[ji][7]);
        *(float4*)(sX + j * 128 + (((2 * pg) ^ jg) << 2))     = lo;
        *(float4*)(sX + j * 128 + (((2 * pg + 1) ^ jg) << 2)) = hi;
    }
}

__global__ __launch_bounds__(128) void pair_kernel(
    const float* __restrict__ aw1, const float* __restrict__ ab1,
    const float* __restrict__ aw2, const float* __restrict__ ab2,
    const float* __restrict__ aw3, const float* __restrict__ ab3,
    const float* __restrict__ ab0, const int* __restrict__ dimp) {
    extern __shared__ __align__(16) char smem_raw[];
    PairSmem* sm = (PairSmem*)smem_raw;
    int dim = read_dim(dimp);
    int p0 = blockIdx.x * BLKP;
    if (p0 >= dim) return;               // uniform block exit
    int b = blockIdx.y, t = threadIdx.x;

    // ---- load weights/biases into shared ----
    {
        const float4* a1v = (const float4*)aw1;
        const float4* a2v = (const float4*)aw2;
        float4* w0v = (float4*)sm->W[0];
        float4* w1v = (float4*)sm->W[1];
#pragma unroll
        for (int i = 0; i < 8; ++i) {
            w0v[t + 128 * i] = a1v[t + 128 * i];
            w1v[t + 128 * i] = a2v[t + 128 * i];
        }
        if (t < 64) {
            sm->b1[t] = ab1[t];
            sm->b2[t] = ab2[t];
            sm->b0[t] = ab0[t];
            sm->Gg[t] = d_Gg[b * 64 + t];
            sm->W3[2 * t + 0] = aw3[2 * t + 0];
            sm->W3[2 * t + 1] = aw3[2 * t + 1];
        }
        if (t < 2) sm->b3[t] = ab3[t];
    }
    __syncthreads();

    // ---- layer 0: build h0 for this block's 128 pairs, store transposed ----
    {
        int p = p0 + t;
        int cnt = d_count[b];
        if (p < cnt) {
            int q = d_order[b * DIMMAX + p];
            int i1 = q / Nn, i2 = q - i1 * Nn;
            const float4* Ga = (const float4*)(d_A + ((size_t)(b * Nn + i1)) * 64);
            const float4* Cc = (const float4*)(d_C + ((size_t)(b * Nn + i2)) * 64);
#pragma unroll
            for (int kk = 0; kk < 16; ++kk) {
                float4 a = Ga[kk], c = Cc[kk];
                int k = 4 * kk;
                sm->X[xaddr(k + 0, t)] = my_tanh(sm->Gg[k + 0] + a.x + c.x);
                sm->X[xaddr(k + 1, t)] = my_tanh(sm->Gg[k + 1] + a.y + c.y);
                sm->X[xaddr(k + 2, t)] = my_tanh(sm->Gg[k + 2] + a.z + c.z);
                sm->X[xaddr(k + 3, t)] = my_tanh(sm->Gg[k + 3] + a.w + c.w);
            }
        } else {
            // zeroed input -> pre-activation = b0
#pragma unroll
            for (int k = 0; k < 64; ++k) sm->X[xaddr(k, t)] = my_tanh(sm->b0[k]);
        }
    }
    __syncthreads();

    int jg = t & 7, pg = t >> 3;
    float acc[8][8];

    // ---- layer 1 ----
    gemm64(sm->X, sm->W[0], sm->b1, acc, jg, pg);
    __syncthreads();
    tanh_store(sm->X, acc, jg, pg);
    __syncthreads();

    // ---- layer 2 ----
    gemm64(sm->X, sm->W[1], sm->b2, acc, jg, pg);
    __syncthreads();
    tanh_store(sm->X, acc, jg, pg);
    __syncthreads();

    // ---- layer 3: per-pair final dot (64 -> 2) ----
    {
        int p = p0 + t;
        if (p < dim) {
            float lg = sm->b3[0], bl = sm->b3[1];
#pragma unroll
            for (int k = 0; k < 64; ++k) {
                float h = sm->X[xaddr(k, t)];
                lg += h * sm->W3[2 * k + 0];
                bl += h * sm->W3[2 * k + 1];
            }
            d_logit[b * DIMMAX + p] = lg;
            d_sig[b * DIMMAX + p] = 1.0f / (1.0f + __expf(-bl));
        }
    }
}

// ---------------- kernel 5: per-batch softmax stats ----------------
__global__ void softmax_kernel(const int* __restrict__ dimp) {
    int b = blockIdx.x, t = threadIdx.x;  // 512 threads
    int dim = read_dim(dimp);
    __shared__ float red[16];
    __shared__ float sM;
    float m = -3.0e38f;
    for (int p = t; p < dim; p += 512) m = fmaxf(m, d_logit[b * DIMMAX + p]);
#pragma unroll
    for (int o = 16; o; o >>= 1) m = fmaxf(m, __shfl_xor_sync(0xffffffffu, m, o));
    if ((t & 31) == 0) red[t >> 5] = m;
    __syncthreads();
    if (t == 0) {
        float mm = red[0];
        for (int i = 1; i < 16; ++i) mm = fmaxf(mm, red[i]);
        sM = mm;
    }
    __syncthreads();
    m = sM;
    float s = 0.f;
    for (int p = t; p < dim; p += 512) s += __expf(d_logit[b * DIMMAX + p] - m);
#pragma unroll
    for (int o = 16; o; o >>= 1) s += __shfl_xor_sync(0xffffffffu, s, o);
    if ((t & 31) == 0) red[t >> 5] = s;
    __syncthreads();
    if (t == 0) {
        float tot = 0.f;
        for (int i = 0; i < 16; ++i) tot += red[i];
        d_bmax[b] = m;
        d_binv[b] = 1.0f / tot;
    }
}

// ---------------- kernel 6: scatter pi / pi_wb into output ----------------
__global__ void scatter_kernel(float* __restrict__ out, const int* __restrict__ dimp) {
    int dim = read_dim(dimp);
    int p = blockIdx.x * 128 + threadIdx.x;
    int b = blockIdx.y;
    if (p >= dim) return;
    if (p >= d_count[b]) return;  // valid == 0 -> contributes zeros only
    int q = d_order[b * DIMMAX + p];
    float pi = __expf(d_logit[b * DIMMAX + p] - d_bmax[b]) * d_binv[b];
    float s = d_sig[b * DIMMAX + p];
    float* ob = out + (size_t)b * 20000;
    ob[q] = pi * s;
    ob[10000 + q] = pi * (1.0f - s);
}

// ---------------- kernel 7: critic value head ----------------
__global__ void critic_kernel(const float* __restrict__ emb,
                              const float* __restrict__ cw0, const float* __restrict__ cb0,
                              const float* __restrict__ cw1, const float* __restrict__ cb1,
                              const float* __restrict__ cw2, const float* __restrict__ cb2,
                              const float* __restrict__ cw3, const float* __restrict__ cb3,
                              float* __restrict__ out, int voff) {
    __shared__ float row[516];
    __shared__ float ha[64];
    __shared__ float hb[64];
    int b = blockIdx.x, t = threadIdx.x;  // 64 threads
    for (int k = t; k < Ff; k += 64) row[k] = emb[(size_t)b * ROWSE * FE + k];
    __syncthreads();
    float acc = cb0[t];
    for (int k = 0; k < Ff; ++k) acc += row[k] * cw0[(size_t)k * 64 + t];
    ha[t] = my_tanh(acc);
    __syncthreads();
    acc = cb1[t];
    for (int k = 0; k < 64; ++k) acc += ha[k] * cw1[k * 64 + t];
    hb[t] = my_tanh(acc);
    __syncthreads();
    acc = cb2[t];
    for (int k = 0; k < 64; ++k) acc += hb[k] * cw2[k * 64 + t];
    ha[t] = my_tanh(acc);
    __syncthreads();
    if (t == 0) {
        float v = cb3[0];
        for (int k = 0; k < 64; ++k) v += ha[k] * cw3[k];
        out[voff + b] = v;
    }
}

// ---------------- launcher ----------------
extern "C" void kernel_launch(void* const* d_in, const int* in_sizes, int n_in,
                              void* d_out, int out_size) {
    const float* emb = (const float*)d_in[0];
    const int* dimp;
    int base;
    if (n_in >= 18 && in_sizes[1] == 1) {   // dict order: emb, dim, actor..., critic...
        dimp = (const int*)d_in[1];
        base = 2;
    } else {                                // signature order: emb, actor..., critic..., dim
        dimp = (const int*)d_in[n_in - 1];
        base = 1;
    }
    const float* aw0 = (const float*)d_in[base + 0];
    const float* ab0 = (const float*)d_in[base + 1];
    const float* aw1 = (const float*)d_in[base + 2];
    const float* ab1 = (const float*)d_in[base + 3];
    const float* aw2 = (const float*)d_in[base + 4];
    const float* ab2 = (const float*)d_in[base + 5];
    const float* aw3 = (const float*)d_in[base + 6];
    const float* ab3 = (const float*)d_in[base + 7];
    const float* cw0 = (const float*)d_in[base + 8];
    const float* cb0 = (const float*)d_in[base + 9];
    const float* cw1 = (const float*)d_in[base + 10];
    const float* cb1 = (const float*)d_in[base + 11];
    const float* cw2 = (const float*)d_in[base + 12];
    const float* cb2 = (const float*)d_in[base + 13];
    const float* cw3 = (const float*)d_in[base + 14];
    const float* cb3 = (const float*)d_in[base + 15];

    float* out = (float*)d_out;
    int voff = out_size - Bz;  // value slot after the filled region (expect 640000)

    static int smem_set = 0;
    if (!smem_set) {
        cudaFuncSetAttribute(pair_kernel, cudaFuncAttributeMaxDynamicSharedMemorySize,
                             PAIR_SMEM_BYTES);
        smem_set = 1;
    }

    cudaMemsetAsync(d_out, 0, (size_t)out_size * sizeof(float), 0);
    scan_kernel<<<Bz, 1024>>>(emb, dimp);
    g_kernel<<<Bz, 64>>>(emb, aw0, ab0);
    ac_kernel<<<dim3(5, Bz), 256>>>(emb, aw0);
    pair_kernel<<<dim3(PBLK, Bz), 128, PAIR_SMEM_BYTES>>>(aw1, ab1, aw2, ab2, aw3, ab3,
                                                          ab0, dimp);
    softmax_kernel<<<Bz, 512>>>(dimp);
    scatter_kernel<<<dim3(PBLK, Bz), 128>>>(out, dimp);
    critic_kernel<<<Bz, 64>>>(emb, cw0, cb0, cw1, cb1, cw2, cb2, cw3, cb3, out, voff);
}

// round 3
// speedup vs baseline: 1.2401x; 1.0243x over previous
#include <cuda_runtime.h>
#include <cstdint>
#include <math.h>

#define Bz     32
#define Nn     100
#define Ff     514
#define FE     614      // 514 feats + 100 mask cols
#define ROWSE  101
#define NN2    10000
#define DIMMAX 10000
#define BLKP   256      // pairs per block in pair kernel
#define PBLK   40       // ceil(DIMMAX/256)

// ---------------- scratch (static device globals; no allocation) ----------------
__device__ int   d_order[Bz * DIMMAX];
__device__ int   d_count[Bz];
__device__ float d_Gg[Bz * 64];
__device__ float d_A[Bz * Nn * 64];
__device__ float d_C[Bz * Nn * 64];
__device__ float d_logit[Bz * DIMMAX];
__device__ float d_sig[Bz * DIMMAX];

// ---------------- small helpers ----------------
__device__ __forceinline__ int read_dim(const int* p) {
    int v = *p;
    if (v < 1 || v > DIMMAX) {            // safety: tolerate float-encoded scalar
        float f = __int_as_float(v);
        v = (int)f;
    }
    if (v < 0) v = 0;
    if (v > DIMMAX) v = DIMMAX;
    return v;
}

__device__ __forceinline__ float my_tanh(float x) {
    // tanh(x) = 1 - 2/(exp(2x)+1)   (exact identity; __expf rel err ~2^-22)
    float e = __expf(2.0f * x);
    return 1.0f - __fdividef(2.0f, e + 1.0f);
}

__device__ __forceinline__ unsigned long long pack2(float a, float b) {
    unsigned long long r;
    asm("mov.b64 %0, {%1, %2};" : "=l"(r) : "f"(a), "f"(b));
    return r;
}
__device__ __forceinline__ void unpack2(unsigned long long v, float& a, float& b) {
    asm("mov.b64 {%0, %1}, %2;" : "=f"(a), "=f"(b) : "l"(v));
}
__device__ __forceinline__ void fma2(unsigned long long& c, unsigned long long a,
                                     unsigned long long b) {
    asm("fma.rn.f32x2 %0, %1, %2, %3;" : "=l"(c) : "l"(a), "l"(b), "l"(c));
}

// ---------------- kernel 1: stable-partition scan -> order/count ----------------
__global__ void scan_kernel(const float* __restrict__ emb, const int* __restrict__ dimp) {
    int b = blockIdx.x, t = threadIdx.x;
    int dim = read_dim(dimp);
    int lane = t & 31, w = t >> 5;
    __shared__ int warp_tot[32];
    __shared__ int s_carry;
    if (t == 0) s_carry = 0;
    __syncthreads();
    for (int c = 0; c < 10; ++c) {
        int idx = c * 1024 + t;
        int flag = 0;
        if (idx < NN2) {
            int i = idx / Nn, j = idx - i * Nn;
            flag = emb[(size_t)(b * ROWSE + 1 + i) * FE + Ff + j] > 0.5f;
        }
        unsigned bal = __ballot_sync(0xffffffffu, flag);
        int wpre = __popc(bal & ((1u << lane) - 1u));
        if (lane == 0) warp_tot[w] = __popc(bal);
        __syncthreads();
        int wbase = 0;
        for (int ww = 0; ww < w; ++ww) wbase += warp_tot[ww];
        int rank = s_carry + wbase + wpre;
        if (flag && rank < dim) d_order[b * DIMMAX + rank] = idx;
        __syncthreads();
        if (t == 0) {
            int tot = 0;
            for (int ww = 0; ww < 32; ++ww) tot += warp_tot[ww];
            s_carry += tot;
        }
        __syncthreads();
    }
    if (t == 0) d_count[b] = s_carry;
}

// ---------------- kernel 2: head = Gg (actor layer-0 g part) + full critic ---------
__global__ void head_kernel(const float* __restrict__ emb,
                            const float* __restrict__ aw0, const float* __restrict__ ab0,
                            const float* __restrict__ cw0, const float* __restrict__ cb0,
                            const float* __restrict__ cw1, const float* __restrict__ cb1,
                            const float* __restrict__ cw2, const float* __restrict__ cb2,
                            const float* __restrict__ cw3, const float* __restrict__ cb3,
                            float* __restrict__ out, int voff) {
    __shared__ float row[516];
    __shared__ float part[256];
    __shared__ float ha[64], hb[64];
    int b = blockIdx.x, t = threadIdx.x;  // 256 threads
    for (int k = t; k < Ff; k += 256) row[k] = emb[(size_t)b * ROWSE * FE + k];
    __syncthreads();
    int j = t & 63, ks = t >> 6;  // 4-way k split
    // Gg = g @ aw0[0:514] + ab0
    {
        float acc = 0.f;
        for (int k = ks; k < Ff; k += 4) acc += row[k] * aw0[(size_t)k * 64 + j];
        part[t] = acc;
    }
    __syncthreads();
    if (t < 64) {
        float s = ab0[j] + part[j] + part[64 + j] + part[128 + j] + part[192 + j];
        d_Gg[b * 64 + j] = s;
    }
    __syncthreads();
    // critic layer 0
    {
        float acc = 0.f;
        for (int k = ks; k < Ff; k += 4) acc += row[k] * cw0[(size_t)k * 64 + j];
        part[t] = acc;
    }
    __syncthreads();
    if (t < 64) {
        float s = cb0[j] + part[j] + part[64 + j] + part[128 + j] + part[192 + j];
        ha[j] = my_tanh(s);
    }
    __syncthreads();
    if (t < 64) {
        float acc = cb1[t];
        for (int k = 0; k < 64; ++k) acc += ha[k] * cw1[k * 64 + t];
        hb[t] = my_tanh(acc);
    }
    __syncthreads();
    if (t < 64) {
        float acc = cb2[t];
        for (int k = 0; k < 64; ++k) acc += hb[k] * cw2[k * 64 + t];
        ha[t] = my_tanh(acc);
    }
    __syncthreads();
    if (t == 0) {
        float v = cb3[0];
        for (int k = 0; k < 64; ++k) v += ha[k] * cw3[k];
        out[voff + b] = v;
    }
}

// ---------------- kernel 3: A = nodes @ W0[514:1028], C = nodes @ W0[1028:1542] ----
__global__ void ac_kernel(const float* __restrict__ emb, const float* __restrict__ w0) {
    __shared__ float rows[20][516];
    int gy = blockIdx.x;          // 0..4  (20 node rows each)
    int b = blockIdx.y;
    int t = threadIdx.x;          // 256
    int R0 = 1 + gy * 20;
    for (int e = t; e < 20 * Ff; e += 256) {
        int r = e / Ff, k = e - r * Ff;
        rows[r][k] = emb[(size_t)(b * ROWSE + R0 + r) * FE + k];
    }
    __syncthreads();
    int j = t & 127, half = t >> 7;
    const float* wcol = w0 + ((j < 64) ? ((size_t)Ff * 64 + j)
                                       : ((size_t)2 * Ff * 64 + (j - 64)));
    float acc[10];
#pragma unroll
    for (int rr = 0; rr < 10; ++rr) acc[rr] = 0.f;
    for (int k4 = 0; k4 < 512; k4 += 4) {
        float wv0 = wcol[(size_t)(k4 + 0) * 64];
        float wv1 = wcol[(size_t)(k4 + 1) * 64];
        float wv2 = wcol[(size_t)(k4 + 2) * 64];
        float wv3 = wcol[(size_t)(k4 + 3) * 64];
#pragma unroll
        for (int rr = 0; rr < 10; ++rr) {
            int r = half + 2 * rr;
            float4 hv = *(const float4*)&rows[r][k4];
            acc[rr] += hv.x * wv0 + hv.y * wv1 + hv.z * wv2 + hv.w * wv3;
        }
    }
    {
        float wv0 = wcol[(size_t)512 * 64], wv1 = wcol[(size_t)513 * 64];
#pragma unroll
        for (int rr = 0; rr < 10; ++rr) {
            int r = half + 2 * rr;
            acc[rr] += rows[r][512] * wv0 + rows[r][513] * wv1;
        }
    }
#pragma unroll
    for (int rr = 0; rr < 10; ++rr) {
        int node = gy * 20 + half + 2 * rr;
        if (j < 64) d_A[((size_t)(b * Nn + node)) * 64 + j] = acc[rr];
        else        d_C[((size_t)(b * Nn + node)) * 64 + (j - 64)] = acc[rr];
    }
}

// ================= pair kernel v3: 256 pairs/block, f32x2 FMA, split-W ==========
struct PairSmem {
    float Wa1[2048], Wb1[2048];   // layer1 weights, j mod 8 < 4 / >= 4 halves
    float Wa2[2048], Wb2[2048];   // layer2
    float X[64 * 256];            // activations [k][pair], XOR-swizzled 16B groups
    float W3[128];                // [k][2]
    float b1[64], b2[64], b0[64], Gg[64];
    float b3[2];
};
#define PAIR_SMEM_BYTES ((int)sizeof(PairSmem))

// element address in X for (row k, pair p): 16B-group XOR swizzle keyed on (k>>3)&7
__device__ __forceinline__ int xaddr(int k, int p) {
    return k * 256 + ((((p) >> 2) ^ ((k >> 3) & 7)) << 2) + (p & 3);
}

__device__ __forceinline__ void gemm64v(const float* __restrict__ sX,
                                        const float* __restrict__ sWa,
                                        const float* __restrict__ sWb,
                                        const float* __restrict__ sb,
                                        unsigned long long (&acc)[4][8],
                                        int jg, int pg) {
#pragma unroll
    for (int j2 = 0; j2 < 4; ++j2) {
        float2 bb = *(const float2*)(sb + jg * 8 + j2 * 2);
        unsigned long long bv = pack2(bb.x, bb.y);
#pragma unroll
        for (int pi = 0; pi < 8; ++pi) acc[j2][pi] = bv;
    }
    for (int k8 = 0; k8 < 8; ++k8) {
        const float* xbase = sX + k8 * 8 * 256;
        int gA = ((2 * pg) ^ k8) << 2;
        int gB = ((2 * pg + 1) ^ k8) << 2;
        const float* wa = sWa + k8 * 8 * 32 + jg * 4;
        const float* wb = sWb + k8 * 8 * 32 + jg * 4;
#pragma unroll
        for (int kk = 0; kk < 8; ++kk) {
            float4 a0 = *(const float4*)(xbase + kk * 256 + gA);
            float4 a1 = *(const float4*)(xbase + kk * 256 + gB);
            ulonglong2 w01 = *(const ulonglong2*)(wa + kk * 32);
            ulonglong2 w23 = *(const ulonglong2*)(wb + kk * 32);
            unsigned long long aa[8];
            aa[0] = pack2(a0.x, a0.x); aa[1] = pack2(a0.y, a0.y);
            aa[2] = pack2(a0.z, a0.z); aa[3] = pack2(a0.w, a0.w);
            aa[4] = pack2(a1.x, a1.x); aa[5] = pack2(a1.y, a1.y);
            aa[6] = pack2(a1.z, a1.z); aa[7] = pack2(a1.w, a1.w);
#pragma unroll
            for (int pi = 0; pi < 8; ++pi) {
                fma2(acc[0][pi], w01.x, aa[pi]);
                fma2(acc[1][pi], w01.y, aa[pi]);
                fma2(acc[2][pi], w23.x, aa[pi]);
                fma2(acc[3][pi], w23.y, aa[pi]);
            }
        }
    }
}

__device__ __forceinline__ void tanh_store(float* __restrict__ sX,
                                           unsigned long long (&acc)[4][8],
                                           int jg, int pg) {
#pragma unroll
    for (int j2 = 0; j2 < 4; ++j2) {
        float lo[8], hi[8];
#pragma unroll
        for (int pi = 0; pi < 8; ++pi) {
            float a, b;
            unpack2(acc[j2][pi], a, b);
            lo[pi] = my_tanh(a);
            hi[pi] = my_tanh(b);
        }
        int jlo = jg * 8 + 2 * j2, jhi = jlo + 1;
        int gA = ((2 * pg) ^ jg) << 2, gB = ((2 * pg + 1) ^ jg) << 2;
        *(float4*)(sX + jlo * 256 + gA) = make_float4(lo[0], lo[1], lo[2], lo[3]);
        *(float4*)(sX + jlo * 256 + gB) = make_float4(lo[4], lo[5], lo[6], lo[7]);
        *(float4*)(sX + jhi * 256 + gA) = make_float4(hi[0], hi[1], hi[2], hi[3]);
        *(float4*)(sX + jhi * 256 + gB) = make_float4(hi[4], hi[5], hi[6], hi[7]);
    }
}

__global__ __launch_bounds__(256, 2) void pair_kernel(
    const float* __restrict__ aw1, const float* __restrict__ ab1,
    const float* __restrict__ aw2, const float* __restrict__ ab2,
    const float* __restrict__ aw3, const float* __restrict__ ab3,
    const float* __restrict__ ab0, const int* __restrict__ dimp) {
    extern __shared__ __align__(16) char smem_raw[];
    PairSmem* sm = (PairSmem*)smem_raw;
    int dim = read_dim(dimp);
    int p0 = blockIdx.x * BLKP;
    if (p0 >= dim) return;               // uniform block exit
    int b = blockIdx.y, t = threadIdx.x;

    // ---- stage weights/biases into shared (split-half layout) ----
    {
        const float4* a1v = (const float4*)aw1;
        const float4* a2v = (const float4*)aw2;
#pragma unroll
        for (int it = 0; it < 4; ++it) {
            int g = t + 256 * it;
            int k = g >> 4, gg = g & 15;
            int half = gg & 1, j8 = gg >> 1;
            int di = k * 8 + j8;
            float4 v1 = a1v[g];
            float4 v2 = a2v[g];
            ((float4*)(half ? sm->Wb1 : sm->Wa1))[di] = v1;
            ((float4*)(half ? sm->Wb2 : sm->Wa2))[di] = v2;
        }
        if (t < 64) {
            sm->b1[t] = ab1[t];
            sm->b2[t] = ab2[t];
            sm->b0[t] = ab0[t];
            sm->Gg[t] = d_Gg[b * 64 + t];
            sm->W3[2 * t + 0] = aw3[2 * t + 0];
            sm->W3[2 * t + 1] = aw3[2 * t + 1];
        }
        if (t < 2) sm->b3[t] = ab3[t];
    }
    __syncthreads();

    // ---- layer 0: build h0 for this block's 256 pairs, store transposed ----
    {
        int p = p0 + t;
        int cnt = d_count[b];
        if (p < cnt) {
            int q = d_order[b * DIMMAX + p];
            int i1 = q / Nn, i2 = q - i1 * Nn;
            const float4* Ga = (const float4*)(d_A + ((size_t)(b * Nn + i1)) * 64);
            const float4* Cc = (const float4*)(d_C + ((size_t)(b * Nn + i2)) * 64);
#pragma unroll
            for (int kk = 0; kk < 16; ++kk) {
                float4 a = Ga[kk], c = Cc[kk];
                int k = 4 * kk;
                sm->X[xaddr(k + 0, t)] = my_tanh(sm->Gg[k + 0] + a.x + c.x);
                sm->X[xaddr(k + 1, t)] = my_tanh(sm->Gg[k + 1] + a.y + c.y);
                sm->X[xaddr(k + 2, t)] = my_tanh(sm->Gg[k + 2] + a.z + c.z);
                sm->X[xaddr(k + 3, t)] = my_tanh(sm->Gg[k + 3] + a.w + c.w);
            }
        } else {
            // zeroed input -> pre-activation = b0
#pragma unroll
            for (int k = 0; k < 64; ++k) sm->X[xaddr(k, t)] = my_tanh(sm->b0[k]);
        }
    }
    __syncthreads();

    int jg = t & 7, pg = t >> 3;
    unsigned long long acc[4][8];

    // ---- layer 1 ----
    gemm64v(sm->X, sm->Wa1, sm->Wb1, sm->b1, acc, jg, pg);
    __syncthreads();
    tanh_store(sm->X, acc, jg, pg);
    __syncthreads();

    // ---- layer 2 ----
    gemm64v(sm->X, sm->Wa2, sm->Wb2, sm->b2, acc, jg, pg);
    __syncthreads();
    tanh_store(sm->X, acc, jg, pg);
    __syncthreads();

    // ---- layer 3: per-pair final dot (64 -> 2) ----
    {
        int p = p0 + t;
        if (p < dim) {
            float lg = sm->b3[0], bl = sm->b3[1];
#pragma unroll
            for (int k = 0; k < 64; ++k) {
                float h = sm->X[xaddr(k, t)];
                lg += h * sm->W3[2 * k + 0];
                bl += h * sm->W3[2 * k + 1];
            }
            d_logit[b * DIMMAX + p] = lg;
            d_sig[b * DIMMAX + p] = 1.0f / (1.0f + __expf(-bl));
        }
    }
}

// ---------------- kernel 5: fused softmax stats + scatter ----------------
__global__ void softscatter_kernel(float* __restrict__ out, const int* __restrict__ dimp) {
    int b = blockIdx.x, t = threadIdx.x;  // 1024 threads
    int dim = read_dim(dimp);
    __shared__ float red[32];
    __shared__ float sM, sInv;
    float m = -3.0e38f;
    for (int p = t; p < dim; p += 1024) m = fmaxf(m, d_logit[b * DIMMAX + p]);
#pragma unroll
    for (int o = 16; o; o >>= 1) m = fmaxf(m, __shfl_xor_sync(0xffffffffu, m, o));
    if ((t & 31) == 0) red[t >> 5] = m;
    __syncthreads();
    if (t == 0) {
        float mm = red[0];
        for (int i = 1; i < 32; ++i) mm = fmaxf(mm, red[i]);
        sM = mm;
    }
    __syncthreads();
    m = sM;
    float s = 0.f;
    for (int p = t; p < dim; p += 1024) s += __expf(d_logit[b * DIMMAX + p] - m);
#pragma unroll
    for (int o = 16; o; o >>= 1) s += __shfl_xor_sync(0xffffffffu, s, o);
    if ((t & 31) == 0) red[t >> 5] = s;
    __syncthreads();
    if (t == 0) {
        float tot = 0.f;
        for (int i = 0; i < 32; ++i) tot += red[i];
        sInv = 1.0f / tot;
    }
    __syncthreads();
    float inv = sInv;
    int cnt = d_count[b];
    int lim = (cnt < dim) ? cnt : dim;
    float* ob = out + (size_t)b * 20000;
    for (int p = t; p < lim; p += 1024) {
        int q = d_order[b * DIMMAX + p];
        float pi = __expf(d_logit[b * DIMMAX + p] - m) * inv;
        float sg = d_sig[b * DIMMAX + p];
        ob[q] = pi * sg;
        ob[10000 + q] = pi * (1.0f - sg);
    }
}

// ---------------- launcher ----------------
extern "C" void kernel_launch(void* const* d_in, const int* in_sizes, int n_in,
                              void* d_out, int out_size) {
    const float* emb = (const float*)d_in[0];
    const int* dimp;
    int base;
    if (n_in >= 18 && in_sizes[1] == 1) {   // dict order: emb, dim, actor..., critic...
        dimp = (const int*)d_in[1];
        base = 2;
    } else {                                // signature order: emb, actor..., critic..., dim
        dimp = (const int*)d_in[n_in - 1];
        base = 1;
    }
    const float* aw0 = (const float*)d_in[base + 0];
    const float* ab0 = (const float*)d_in[base + 1];
    const float* aw1 = (const float*)d_in[base + 2];
    const float* ab1 = (const float*)d_in[base + 3];
    const float* aw2 = (const float*)d_in[base + 4];
    const float* ab2 = (const float*)d_in[base + 5];
    const float* aw3 = (const float*)d_in[base + 6];
    const float* ab3 = (const float*)d_in[base + 7];
    const float* cw0 = (const float*)d_in[base + 8];
    const float* cb0 = (const float*)d_in[base + 9];
    const float* cw1 = (const float*)d_in[base + 10];
    const float* cb1 = (const float*)d_in[base + 11];
    const float* cw2 = (const float*)d_in[base + 12];
    const float* cb2 = (const float*)d_in[base + 13];
    const float* cw3 = (const float*)d_in[base + 14];
    const float* cb3 = (const float*)d_in[base + 15];

    float* out = (float*)d_out;
    int voff = out_size - Bz;  // value slot after the filled region (expect 640000)

    static int smem_set = 0;
    if (!smem_set) {
        cudaFuncSetAttribute(pair_kernel, cudaFuncAttributeMaxDynamicSharedMemorySize,
                             PAIR_SMEM_BYTES);
        smem_set = 1;
    }

    cudaMemsetAsync(d_out, 0, (size_t)out_size * sizeof(float), 0);
    scan_kernel<<<Bz, 1024>>>(emb, dimp);
    head_kernel<<<Bz, 256>>>(emb, aw0, ab0, cw0, cb0, cw1, cb1, cw2, cb2, cw3, cb3,
                             out, voff);
    ac_kernel<<<dim3(5, Bz), 256>>>(emb, aw0);
    pair_kernel<<<dim3(PBLK, Bz), 256, PAIR_SMEM_BYTES>>>(aw1, ab1, aw2, ab2, aw3, ab3,
                                                          ab0, dimp);
    softscatter_kernel<<<Bz, 1024>>>(out, dimp);
}

// round 4
// speedup vs baseline: 1.4367x; 1.1585x over previous
#include <cuda_runtime.h>
#include <cstdint>
#include <math.h>

#define Bz     32
#define Nn     100
#define Ff     514
#define FE     614      // 514 feats + 100 mask cols
#define ROWSE  101
#define NN2    10000
#define DIMMAX 10000
#define BLKP   256      // pairs per block in pair kernel
#define PBLK   40       // ceil(DIMMAX/256)

// ---------------- scratch (static device globals; no allocation) ----------------
__device__ int   d_order[Bz * DIMMAX];
__device__ int   d_count[Bz];
__device__ float d_Gg[Bz * 64];
__device__ float d_A[Bz * Nn * 64];
__device__ float d_C[Bz * Nn * 64];
__device__ float d_logit[Bz * DIMMAX];
__device__ float d_sig[Bz * DIMMAX];

// ---------------- small helpers ----------------
__device__ __forceinline__ int read_dim(const int* p) {
    int v = *p;
    if (v < 1 || v > DIMMAX) {            // safety: tolerate float-encoded scalar
        float f = __int_as_float(v);
        v = (int)f;
    }
    if (v < 0) v = 0;
    if (v > DIMMAX) v = DIMMAX;
    return v;
}

__device__ __forceinline__ float my_tanh(float x) {
    // tanh(x) = 1 - 2/(exp(2x)+1)   (exact identity; __expf rel err ~2^-22)
    float e = __expf(2.0f * x);
    return 1.0f - __fdividef(2.0f, e + 1.0f);
}

// ---------------- kernel 1: stable-partition scan -> order/count (1-pass) -------
__global__ void scan_kernel(const float* __restrict__ emb, const int* __restrict__ dimp) {
    int b = blockIdx.x, t = threadIdx.x;  // 1024 threads
    int lane = t & 31, w = t >> 5;
    int dim = read_dim(dimp);
    __shared__ unsigned bal[10][32];
    __shared__ int pre[320];
    __shared__ int wsum[10];
    // phase 1: all ballots
#pragma unroll
    for (int c = 0; c < 10; ++c) {
        int idx = c * 1024 + t;
        int flag = 0;
        if (idx < NN2) {
            int i = idx / Nn, j = idx - i * Nn;
            flag = emb[(size_t)(b * ROWSE + 1 + i) * FE + Ff + j] > 0.5f;
        }
        unsigned bl = __ballot_sync(0xffffffffu, flag);
        if (lane == 0) bal[c][w] = bl;
    }
    __syncthreads();
    // phase 2: exclusive scan over 320 (chunk, warp) counts
    if (t < 320) {
        int v = __popc(bal[t >> 5][t & 31]);
        int p = v;
#pragma unroll
        for (int o = 1; o < 32; o <<= 1) {
            int n = __shfl_up_sync(0xffffffffu, p, o);
            if (lane >= o) p += n;
        }
        if (lane == 31) wsum[t >> 5] = p;
        pre[t] = p - v;
    }
    __syncthreads();
    if (t < 320) {
        int base = 0;
        for (int k = 0; k < (t >> 5); ++k) base += wsum[k];
        pre[t] += base;
    }
    __syncthreads();
    // phase 3: write ranks
#pragma unroll
    for (int c = 0; c < 10; ++c) {
        unsigned bl = bal[c][w];
        if ((bl >> lane) & 1u) {
            int rank = pre[c * 32 + w] + __popc(bl & ((1u << lane) - 1u));
            if (rank < dim) d_order[b * DIMMAX + rank] = c * 1024 + t;
        }
    }
    if (t == 0) d_count[b] = pre[319] + __popc(bal[9][31]);
}

// ---------------- kernel 2: head = Gg (actor layer-0 g part) + full critic ---------
__global__ void head_kernel(const float* __restrict__ emb,
                            const float* __restrict__ aw0, const float* __restrict__ ab0,
                            const float* __restrict__ cw0, const float* __restrict__ cb0,
                            const float* __restrict__ cw1, const float* __restrict__ cb1,
                            const float* __restrict__ cw2, const float* __restrict__ cb2,
                            const float* __restrict__ cw3, const float* __restrict__ cb3,
                            float* __restrict__ out, int voff) {
    __shared__ float row[516];
    __shared__ float part[256];
    __shared__ float ha[64], hb[64];
    int b = blockIdx.x, t = threadIdx.x;  // 256 threads
    for (int k = t; k < Ff; k += 256) row[k] = emb[(size_t)b * ROWSE * FE + k];
    __syncthreads();
    int j = t & 63, ks = t >> 6;  // 4-way k split
    {
        float acc = 0.f;
        for (int k = ks; k < Ff; k += 4) acc += row[k] * aw0[(size_t)k * 64 + j];
        part[t] = acc;
    }
    __syncthreads();
    if (t < 64) {
        float s = ab0[j] + part[j] + part[64 + j] + part[128 + j] + part[192 + j];
        d_Gg[b * 64 + j] = s;
    }
    __syncthreads();
    {
        float acc = 0.f;
        for (int k = ks; k < Ff; k += 4) acc += row[k] * cw0[(size_t)k * 64 + j];
        part[t] = acc;
    }
    __syncthreads();
    if (t < 64) {
        float s = cb0[j] + part[j] + part[64 + j] + part[128 + j] + part[192 + j];
        ha[j] = my_tanh(s);
    }
    __syncthreads();
    if (t < 64) {
        float acc = cb1[t];
        for (int k = 0; k < 64; ++k) acc += ha[k] * cw1[k * 64 + t];
        hb[t] = my_tanh(acc);
    }
    __syncthreads();
    if (t < 64) {
        float acc = cb2[t];
        for (int k = 0; k < 64; ++k) acc += hb[k] * cw2[k * 64 + t];
        ha[t] = my_tanh(acc);
    }
    __syncthreads();
    if (t == 0) {
        float v = cb3[0];
        for (int k = 0; k < 64; ++k) v += ha[k] * cw3[k];
        out[voff + b] = v;
    }
}

// ---------------- kernel 3: A = nodes @ W0[514:1028], C = nodes @ W0[1028:1542] ----
__global__ void ac_kernel(const float* __restrict__ emb, const float* __restrict__ w0) {
    __shared__ float rows[20][516];
    int gy = blockIdx.x;          // 0..4  (20 node rows each)
    int b = blockIdx.y;
    int t = threadIdx.x;          // 256
    int R0 = 1 + gy * 20;
    for (int e = t; e < 20 * Ff; e += 256) {
        int r = e / Ff, k = e - r * Ff;
        rows[r][k] = emb[(size_t)(b * ROWSE + R0 + r) * FE + k];
    }
    __syncthreads();
    int j = t & 127, half = t >> 7;
    const float* wcol = w0 + ((j < 64) ? ((size_t)Ff * 64 + j)
                                       : ((size_t)2 * Ff * 64 + (j - 64)));
    float acc[10];
#pragma unroll
    for (int rr = 0; rr < 10; ++rr) acc[rr] = 0.f;
    for (int k4 = 0; k4 < 512; k4 += 4) {
        float wv0 = wcol[(size_t)(k4 + 0) * 64];
        float wv1 = wcol[(size_t)(k4 + 1) * 64];
        float wv2 = wcol[(size_t)(k4 + 2) * 64];
        float wv3 = wcol[(size_t)(k4 + 3) * 64];
#pragma unroll
        for (int rr = 0; rr < 10; ++rr) {
            int r = half + 2 * rr;
            float4 hv = *(const float4*)&rows[r][k4];
            acc[rr] += hv.x * wv0 + hv.y * wv1 + hv.z * wv2 + hv.w * wv3;
        }
    }
    {
        float wv0 = wcol[(size_t)512 * 64], wv1 = wcol[(size_t)513 * 64];
#pragma unroll
        for (int rr = 0; rr < 10; ++rr) {
            int r = half + 2 * rr;
            acc[rr] += rows[r][512] * wv0 + rows[r][513] * wv1;
        }
    }
#pragma unroll
    for (int rr = 0; rr < 10; ++rr) {
        int node = gy * 20 + half + 2 * rr;
        if (j < 64) d_A[((size_t)(b * Nn + node)) * 64 + j] = acc[rr];
        else        d_C[((size_t)(b * Nn + node)) * 64 + (j - 64)] = acc[rr];
    }
}

// ================= pair kernel v4: 256 pairs/block, scalar FFMA, split-W ==========
struct PairSmem {
    float Wa1[2048], Wb1[2048];   // layer1 weights, j mod 8 < 4 / >= 4 halves
    float Wa2[2048], Wb2[2048];   // layer2
    float X[64 * 256];            // activations [k][pair], XOR-swizzled 16B groups
    float W3[128];                // [k][2]
    float b1[64], b2[64], b0[64], Gg[64];
    float b3[2];
};
#define PAIR_SMEM_BYTES ((int)sizeof(PairSmem))

// element address in X for (row k, pair p): 16B-group XOR swizzle keyed on (k>>3)&7
__device__ __forceinline__ int xaddr(int k, int p) {
    return k * 256 + ((((p) >> 2) ^ ((k >> 3) & 7)) << 2) + (p & 3);
}

__device__ __forceinline__ void gemm64s(const float* __restrict__ sX,
                                        const float* __restrict__ sWa,
                                        const float* __restrict__ sWb,
                                        const float* __restrict__ sb,
                                        float (&acc)[8][8], int jg, int pg) {
#pragma unroll
    for (int ji = 0; ji < 8; ++ji) {
        float bj = sb[jg * 8 + ji];
#pragma unroll
        for (int pi = 0; pi < 8; ++pi) acc[ji][pi] = bj;
    }
    for (int k8 = 0; k8 < 8; ++k8) {
        const float* xbase = sX + k8 * 8 * 256;
        int gA = ((2 * pg) ^ k8) << 2;
        int gB = ((2 * pg + 1) ^ k8) << 2;
        const float* wa = sWa + k8 * 8 * 32 + jg * 4;
        const float* wb = sWb + k8 * 8 * 32 + jg * 4;
#pragma unroll
        for (int kk = 0; kk < 8; ++kk) {
            float4 a0 = *(const float4*)(xbase + kk * 256 + gA);
            float4 a1 = *(const float4*)(xbase + kk * 256 + gB);
            float4 w0 = *(const float4*)(wa + kk * 32);
            float4 w1 = *(const float4*)(wb + kk * 32);
            float as[8] = {a0.x, a0.y, a0.z, a0.w, a1.x, a1.y, a1.z, a1.w};
            float ws[8] = {w0.x, w0.y, w0.z, w0.w, w1.x, w1.y, w1.z, w1.w};
#pragma unroll
            for (int ji = 0; ji < 8; ++ji)
#pragma unroll
                for (int pi = 0; pi < 8; ++pi)
                    acc[ji][pi] += ws[ji] * as[pi];
        }
    }
}

__device__ __forceinline__ void tanh_store(float* __restrict__ sX,
                                           float (&acc)[8][8], int jg, int pg) {
    int gA = ((2 * pg) ^ jg) << 2, gB = ((2 * pg + 1) ^ jg) << 2;
#pragma unroll
    for (int ji = 0; ji < 8; ++ji) {
        int j = jg * 8 + ji;
        float4 lo, hi;
        lo.x = my_tanh(acc[ji][0]); lo.y = my_tanh(acc[ji][1]);
        lo.z = my_tanh(acc[ji][2]); lo.w = my_tanh(acc[ji][3]);
        hi.x = my_tanh(acc[ji][4]); hi.y = my_tanh(acc[ji][5]);
        hi.z = my_tanh(acc[ji][6]); hi.w = my_tanh(acc[ji][7]);
        *(float4*)(sX + j * 256 + gA) = lo;
        *(float4*)(sX + j * 256 + gB) = hi;
    }
}

__global__ __launch_bounds__(256, 2) void pair_kernel(
    const float* __restrict__ aw1, const float* __restrict__ ab1,
    const float* __restrict__ aw2, const float* __restrict__ ab2,
    const float* __restrict__ aw3, const float* __restrict__ ab3,
    const float* __restrict__ ab0, const int* __restrict__ dimp) {
    extern __shared__ __align__(16) char smem_raw[];
    PairSmem* sm = (PairSmem*)smem_raw;
    int dim = read_dim(dimp);
    int p0 = blockIdx.x * BLKP;
    if (p0 >= dim) return;               // uniform block exit
    int b = blockIdx.y, t = threadIdx.x;

    // ---- stage weights/biases into shared (split-half layout) ----
    {
        const float4* a1v = (const float4*)aw1;
        const float4* a2v = (const float4*)aw2;
#pragma unroll
        for (int it = 0; it < 4; ++it) {
            int g = t + 256 * it;
            int k = g >> 4, gg = g & 15;
            int half = gg & 1, j8 = gg >> 1;
            int di = k * 8 + j8;
            float4 v1 = a1v[g];
            float4 v2 = a2v[g];
            ((float4*)(half ? sm->Wb1 : sm->Wa1))[di] = v1;
            ((float4*)(half ? sm->Wb2 : sm->Wa2))[di] = v2;
        }
        if (t < 64) {
            sm->b1[t] = ab1[t];
            sm->b2[t] = ab2[t];
            sm->b0[t] = ab0[t];
            sm->Gg[t] = d_Gg[b * 64 + t];
            sm->W3[2 * t + 0] = aw3[2 * t + 0];
            sm->W3[2 * t + 1] = aw3[2 * t + 1];
        }
        if (t < 2) sm->b3[t] = ab3[t];
    }
    __syncthreads();

    // ---- layer 0: build h0 for this block's 256 pairs, store transposed ----
    {
        int p = p0 + t;
        int cnt = d_count[b];
        if (p < cnt) {
            int q = d_order[b * DIMMAX + p];
            int i1 = q / Nn, i2 = q - i1 * Nn;
            const float4* Ga = (const float4*)(d_A + ((size_t)(b * Nn + i1)) * 64);
            const float4* Cc = (const float4*)(d_C + ((size_t)(b * Nn + i2)) * 64);
#pragma unroll
            for (int kk = 0; kk < 16; ++kk) {
                float4 a = Ga[kk], c = Cc[kk];
                int k = 4 * kk;
                sm->X[xaddr(k + 0, t)] = my_tanh(sm->Gg[k + 0] + a.x + c.x);
                sm->X[xaddr(k + 1, t)] = my_tanh(sm->Gg[k + 1] + a.y + c.y);
                sm->X[xaddr(k + 2, t)] = my_tanh(sm->Gg[k + 2] + a.z + c.z);
                sm->X[xaddr(k + 3, t)] = my_tanh(sm->Gg[k + 3] + a.w + c.w);
            }
        } else {
            // zeroed input -> pre-activation = b0
#pragma unroll
            for (int k = 0; k < 64; ++k) sm->X[xaddr(k, t)] = my_tanh(sm->b0[k]);
        }
    }
    __syncthreads();

    int jg = t & 7, pg = t >> 3;
    float acc[8][8];

    // ---- layer 1 ----
    gemm64s(sm->X, sm->Wa1, sm->Wb1, sm->b1, acc, jg, pg);
    __syncthreads();
    tanh_store(sm->X, acc, jg, pg);
    __syncthreads();

    // ---- layer 2 ----
    gemm64s(sm->X, sm->Wa2, sm->Wb2, sm->b2, acc, jg, pg);
    __syncthreads();
    tanh_store(sm->X, acc, jg, pg);
    __syncthreads();

    // ---- layer 3: per-pair final dot (64 -> 2) ----
    {
        int p = p0 + t;
        if (p < dim) {
            float lg = sm->b3[0], bl = sm->b3[1];
#pragma unroll
            for (int k = 0; k < 64; ++k) {
                float h = sm->X[xaddr(k, t)];
                lg += h * sm->W3[2 * k + 0];
                bl += h * sm->W3[2 * k + 1];
            }
            d_logit[b * DIMMAX + p] = lg;
            d_sig[b * DIMMAX + p] = 1.0f / (1.0f + __expf(-bl));
        }
    }
}

// ---------------- kernel 5: fused softmax stats + scatter ----------------
__global__ void softscatter_kernel(float* __restrict__ out, const int* __restrict__ dimp) {
    int b = blockIdx.x, t = threadIdx.x;  // 1024 threads
    int dim = read_dim(dimp);
    __shared__ float red[32];
    __shared__ float sM, sInv;
    float m = -3.0e38f;
    for (int p = t; p < dim; p += 1024) m = fmaxf(m, d_logit[b * DIMMAX + p]);
#pragma unroll
    for (int o = 16; o; o >>= 1) m = fmaxf(m, __shfl_xor_sync(0xffffffffu, m, o));
    if ((t & 31) == 0) red[t >> 5] = m;
    __syncthreads();
    if (t == 0) {
        float mm = red[0];
        for (int i = 1; i < 32; ++i) mm = fmaxf(mm, red[i]);
        sM = mm;
    }
    __syncthreads();
    m = sM;
    float s = 0.f;
    for (int p = t; p < dim; p += 1024) s += __expf(d_logit[b * DIMMAX + p] - m);
#pragma unroll
    for (int o = 16; o; o >>= 1) s += __shfl_xor_sync(0xffffffffu, s, o);
    if ((t & 31) == 0) red[t >> 5] = s;
    __syncthreads();
    if (t == 0) {
        float tot = 0.f;
        for (int i = 0; i < 32; ++i) tot += red[i];
        sInv = 1.0f / tot;
    }
    __syncthreads();
    float inv = sInv;
    int cnt = d_count[b];
    int lim = (cnt < dim) ? cnt : dim;
    float* ob = out + (size_t)b * 20000;
    for (int p = t; p < lim; p += 1024) {
        int q = d_order[b * DIMMAX + p];
        float pi = __expf(d_logit[b * DIMMAX + p] - m) * inv;
        float sg = d_sig[b * DIMMAX + p];
        ob[q] = pi * sg;
        ob[10000 + q] = pi * (1.0f - sg);
    }
}

// ---------------- launcher (forked capture: scan || ac || memset+head) ----------
extern "C" void kernel_launch(void* const* d_in, const int* in_sizes, int n_in,
                              void* d_out, int out_size) {
    const float* emb = (const float*)d_in[0];
    const int* dimp;
    int base;
    if (n_in >= 18 && in_sizes[1] == 1) {   // dict order: emb, dim, actor..., critic...
        dimp = (const int*)d_in[1];
        base = 2;
    } else {                                // signature order: emb, actor..., critic..., dim
        dimp = (const int*)d_in[n_in - 1];
        base = 1;
    }
    const float* aw0 = (const float*)d_in[base + 0];
    const float* ab0 = (const float*)d_in[base + 1];
    const float* aw1 = (const float*)d_in[base + 2];
    const float* ab1 = (const float*)d_in[base + 3];
    const float* aw2 = (const float*)d_in[base + 4];
    const float* ab2 = (const float*)d_in[base + 5];
    const float* aw3 = (const float*)d_in[base + 6];
    const float* ab3 = (const float*)d_in[base + 7];
    const float* cw0 = (const float*)d_in[base + 8];
    const float* cb0 = (const float*)d_in[base + 9];
    const float* cw1 = (const float*)d_in[base + 10];
    const float* cb1 = (const float*)d_in[base + 11];
    const float* cw2 = (const float*)d_in[base + 12];
    const float* cb2 = (const float*)d_in[base + 13];
    const float* cw3 = (const float*)d_in[base + 14];
    const float* cb3 = (const float*)d_in[base + 15];

    float* out = (float*)d_out;
    int voff = out_size - Bz;  // value slot after the filled region (expect 640000)

    static cudaStream_t s1 = 0, s2 = 0;
    static cudaEvent_t eF = 0, e1 = 0, e2 = 0;
    static int init_done = 0;
    if (!init_done) {
        cudaFuncSetAttribute(pair_kernel, cudaFuncAttributeMaxDynamicSharedMemorySize,
                             PAIR_SMEM_BYTES);
        cudaStreamCreateWithFlags(&s1, cudaStreamNonBlocking);
        cudaStreamCreateWithFlags(&s2, cudaStreamNonBlocking);
        cudaEventCreateWithFlags(&eF, cudaEventDisableTiming);
        cudaEventCreateWithFlags(&e1, cudaEventDisableTiming);
        cudaEventCreateWithFlags(&e2, cudaEventDisableTiming);
        init_done = 1;
    }

    // fork
    cudaEventRecord(eF, 0);
    cudaStreamWaitEvent(s1, eF, 0);
    cudaStreamWaitEvent(s2, eF, 0);

    scan_kernel<<<Bz, 1024, 0, s1>>>(emb, dimp);
    cudaEventRecord(e1, s1);

    ac_kernel<<<dim3(5, Bz), 256, 0, s2>>>(emb, aw0);
    cudaEventRecord(e2, s2);

    cudaMemsetAsync(d_out, 0, (size_t)out_size * sizeof(float), 0);
    head_kernel<<<Bz, 256, 0, 0>>>(emb, aw0, ab0, cw0, cb0, cw1, cb1, cw2, cb2,
                                   cw3, cb3, out, voff);

    // join
    cudaStreamWaitEvent(0, e1, 0);
    cudaStreamWaitEvent(0, e2, 0);

    pair_kernel<<<dim3(PBLK, Bz), 256, PAIR_SMEM_BYTES>>>(aw1, ab1, aw2, ab2, aw3, ab3,
                                                          ab0, dimp);
    softscatter_kernel<<<Bz, 1024>>>(out, dimp);
}

// round 5
// speedup vs baseline: 1.4396x; 1.0021x over previous
#include <cuda_runtime.h>
#include <cstdint>
#include <math.h>

#define Bz     32
#define Nn     100
#define Ff     514
#define FE     614      // 514 feats + 100 mask cols
#define ROWSE  101
#define NN2    10000
#define DIMMAX 10000
#define BLKP   128      // pairs per block in pair kernel
#define PBLK   79       // ceil(DIMMAX/128)

// ---------------- scratch (static device globals; no allocation) ----------------
__device__ int   d_order[Bz * DIMMAX];
__device__ int   d_count[Bz];
__device__ float d_Gg[Bz * 64];
__device__ float d_A[Bz * Nn * 64];
__device__ float d_C[Bz * Nn * 64];
__device__ float d_logit[Bz * DIMMAX];   // holds e = exp(logit - shift)
__device__ float d_sig[Bz * DIMMAX];

// ---------------- small helpers ----------------
__device__ __forceinline__ int read_dim(const int* p) {
    int v = *p;
    if (v < 1 || v > DIMMAX) {            // safety: tolerate float-encoded scalar
        float f = __int_as_float(v);
        v = (int)f;
    }
    if (v < 0) v = 0;
    if (v > DIMMAX) v = DIMMAX;
    return v;
}

__device__ __forceinline__ float my_tanh(float x) {
    // tanh(x) = 1 - 2/(exp(2x)+1)   (exact identity; __expf rel err ~2^-22)
    float e = __expf(2.0f * x);
    return 1.0f - __fdividef(2.0f, e + 1.0f);
}

// ================= prep kernel: fused scan / head / ac via blockIdx.y ===========
// dynamic smem: 41280 bytes (ac role's 20x516 tile is the max)

__device__ void scan_role(const float* __restrict__ emb, int b, int dim, char* sh) {
    int t = threadIdx.x;           // 256
    int lane = t & 31, w = t >> 5; // 8 warps
    unsigned* bal = (unsigned*)sh;         // [320]
    int* pre = (int*)(sh + 320 * 4);       // [320]
    // phase 1: ballots for 40 chunks of 256
#pragma unroll
    for (int c = 0; c < 40; ++c) {
        int idx = c * 256 + t;
        int flag = 0;
        if (idx < NN2) {
            int i = idx / Nn, j = idx - i * Nn;
            flag = emb[(size_t)(b * ROWSE + 1 + i) * FE + Ff + j] > 0.5f;
        }
        unsigned bl = __ballot_sync(0xffffffffu, flag);
        if (lane == 0) bal[c * 8 + w] = bl;
    }
    __syncthreads();
    // phase 2: warp 0 does exclusive scan over 320 counts (10 per lane)
    if (t < 32) {
        int loc[10];
        int s = 0;
#pragma unroll
        for (int k = 0; k < 10; ++k) {
            int v = __popc(bal[lane * 10 + k]);
            loc[k] = s;
            s += v;
        }
        int p = s;
#pragma unroll
        for (int o = 1; o < 32; o <<= 1) {
            int n = __shfl_up_sync(0xffffffffu, p, o);
            if (lane >= o) p += n;
        }
        int off = p - s;
#pragma unroll
        for (int k = 0; k < 10; ++k) pre[lane * 10 + k] = off + loc[k];
        if (lane == 31) d_count[b] = p;
    }
    __syncthreads();
    // phase 3: write ranks
#pragma unroll
    for (int c = 0; c < 40; ++c) {
        unsigned bl = bal[c * 8 + w];
        if ((bl >> lane) & 1u) {
            int rank = pre[c * 8 + w] + __popc(bl & ((1u << lane) - 1u));
            if (rank < dim) d_order[b * DIMMAX + rank] = c * 256 + t;
        }
    }
}

__device__ void head_role(const float* __restrict__ emb,
                          const float* __restrict__ aw0, const float* __restrict__ ab0,
                          const float* __restrict__ cw0, const float* __restrict__ cb0,
                          const float* __restrict__ cw1, const float* __restrict__ cb1,
                          const float* __restrict__ cw2, const float* __restrict__ cb2,
                          const float* __restrict__ cw3, const float* __restrict__ cb3,
                          float* __restrict__ out, int voff, int b, char* sh) {
    float* row = (float*)sh;              // [516]
    float* part = row + 516;              // [256]
    float* ha = part + 256;               // [64]
    float* hb = ha + 64;                  // [64]
    int t = threadIdx.x;                  // 256
    for (int k = t; k < Ff; k += 256) row[k] = emb[(size_t)b * ROWSE * FE + k];
    __syncthreads();
    int j = t & 63, ks = t >> 6;  // 4-way k split
    {
        float acc = 0.f;
        for (int k = ks; k < Ff; k += 4) acc += row[k] * aw0[(size_t)k * 64 + j];
        part[t] = acc;
    }
    __syncthreads();
    if (t < 64) {
        float s = ab0[j] + part[j] + part[64 + j] + part[128 + j] + part[192 + j];
        d_Gg[b * 64 + j] = s;
    }
    __syncthreads();
    {
        float acc = 0.f;
        for (int k = ks; k < Ff; k += 4) acc += row[k] * cw0[(size_t)k * 64 + j];
        part[t] = acc;
    }
    __syncthreads();
    if (t < 64) {
        float s = cb0[j] + part[j] + part[64 + j] + part[128 + j] + part[192 + j];
        ha[j] = my_tanh(s);
    }
    __syncthreads();
    if (t < 64) {
        float acc = cb1[t];
        for (int k = 0; k < 64; ++k) acc += ha[k] * cw1[k * 64 + t];
        hb[t] = my_tanh(acc);
    }
    __syncthreads();
    if (t < 64) {
        float acc = cb2[t];
        for (int k = 0; k < 64; ++k) acc += hb[k] * cw2[k * 64 + t];
        ha[t] = my_tanh(acc);
    }
    __syncthreads();
    if (t == 0) {
        float v = cb3[0];
        for (int k = 0; k < 64; ++k) v += ha[k] * cw3[k];
        out[voff + b] = v;
    }
}

__device__ void ac_role(const float* __restrict__ emb, const float* __restrict__ w0,
                        int b, int gy, char* sh) {
    float (*rows)[516] = (float (*)[516])sh;   // 20 x 516
    int t = threadIdx.x;          // 256
    int R0 = 1 + gy * 20;
    for (int e = t; e < 20 * Ff; e += 256) {
        int r = e / Ff, k = e - r * Ff;
        rows[r][k] = emb[(size_t)(b * ROWSE + R0 + r) * FE + k];
    }
    __syncthreads();
    int j = t & 127, half = t >> 7;
    const float* wcol = w0 + ((j < 64) ? ((size_t)Ff * 64 + j)
                                       : ((size_t)2 * Ff * 64 + (j - 64)));
    float acc[10];
#pragma unroll
    for (int rr = 0; rr < 10; ++rr) acc[rr] = 0.f;
    for (int k4 = 0; k4 < 512; k4 += 4) {
        float wv0 = wcol[(size_t)(k4 + 0) * 64];
        float wv1 = wcol[(size_t)(k4 + 1) * 64];
        float wv2 = wcol[(size_t)(k4 + 2) * 64];
        float wv3 = wcol[(size_t)(k4 + 3) * 64];
#pragma unroll
        for (int rr = 0; rr < 10; ++rr) {
            int r = half + 2 * rr;
            float4 hv = *(const float4*)&rows[r][k4];
            acc[rr] += hv.x * wv0 + hv.y * wv1 + hv.z * wv2 + hv.w * wv3;
        }
    }
    {
        float wv0 = wcol[(size_t)512 * 64], wv1 = wcol[(size_t)513 * 64];
#pragma unroll
        for (int rr = 0; rr < 10; ++rr) {
            int r = half + 2 * rr;
            acc[rr] += rows[r][512] * wv0 + rows[r][513] * wv1;
        }
    }
#pragma unroll
    for (int rr = 0; rr < 10; ++rr) {
        int node = gy * 20 + half + 2 * rr;
        if (j < 64) d_A[((size_t)(b * Nn + node)) * 64 + j] = acc[rr];
        else        d_C[((size_t)(b * Nn + node)) * 64 + (j - 64)] = acc[rr];
    }
}

__global__ void prep_kernel(const float* __restrict__ emb,
                            const float* __restrict__ aw0, const float* __restrict__ ab0,
                            const float* __restrict__ cw0, const float* __restrict__ cb0,
                            const float* __restrict__ cw1, const float* __restrict__ cb1,
                            const float* __restrict__ cw2, const float* __restrict__ cb2,
                            const float* __restrict__ cw3, const float* __restrict__ cb3,
                            float* __restrict__ out, int voff,
                            const int* __restrict__ dimp) {
    extern __shared__ __align__(16) char sh[];
    int b = blockIdx.x;
    int role = blockIdx.y;
    if (role == 0) {
        scan_role(emb, b, read_dim(dimp), sh);
    } else if (role == 1) {
        head_role(emb, aw0, ab0, cw0, cb0, cw1, cb1, cw2, cb2, cw3, cb3, out, voff, b, sh);
    } else {
        ac_role(emb, aw0, b, role - 2, sh);
    }
}
#define PREP_SMEM 41280

// ================= pair kernel v5: 128 pairs/block, 256 threads, 8x4 tiles ======
struct PairSmem {
    float Wa1[2048], Wb1[2048];   // layer1 weights, j mod 8 < 4 / >= 4 halves
    float Wa2[2048], Wb2[2048];   // layer2
    float X[64 * 128];            // activations [k][pair], XOR-swizzled 16B groups
    float W3[128];                // [k][2]
    float b1[64], b2[64], b0[64], Gg[64];
    float b3[2];
};
#define PAIR_SMEM_BYTES ((int)sizeof(PairSmem))

// element address in X for (row k, pair p): 16B-group XOR swizzle keyed on (k>>3)&7
__device__ __forceinline__ int xaddr(int k, int p) {
    return k * 128 + ((((p) >> 2) ^ ((k >> 3) & 7)) << 2) + (p & 3);
}

__device__ __forceinline__ void gemm64s(const float* __restrict__ sX,
                                        const float* __restrict__ sWa,
                                        const float* __restrict__ sWb,
                                        const float* __restrict__ sb,
                                        float (&acc)[8][4], int jg, int pg) {
#pragma unroll
    for (int ji = 0; ji < 8; ++ji) {
        float bj = sb[jg * 8 + ji];
#pragma unroll
        for (int pi = 0; pi < 4; ++pi) acc[ji][pi] = bj;
    }
    for (int k8 = 0; k8 < 8; ++k8) {
        const float* xbase = sX + k8 * 8 * 128 + ((pg ^ k8) << 2);
        const float* wa = sWa + k8 * 8 * 32 + jg * 4;
        const float* wb = sWb + k8 * 8 * 32 + jg * 4;
#pragma unroll
        for (int kk = 0; kk < 8; ++kk) {
            float4 a = *(const float4*)(xbase + kk * 128);
            float4 w0 = *(const float4*)(wa + kk * 32);
            float4 w1 = *(const float4*)(wb + kk * 32);
            float as[4] = {a.x, a.y, a.z, a.w};
            float ws[8] = {w0.x, w0.y, w0.z, w0.w, w1.x, w1.y, w1.z, w1.w};
#pragma unroll
            for (int ji = 0; ji < 8; ++ji)
#pragma unroll
                for (int pi = 0; pi < 4; ++pi)
                    acc[ji][pi] += ws[ji] * as[pi];
        }
    }
}

__device__ __forceinline__ void tanh_store(float* __restrict__ sX,
                                           float (&acc)[8][4], int jg, int pg) {
    int g = (pg ^ jg) << 2;
#pragma unroll
    for (int ji = 0; ji < 8; ++ji) {
        int j = jg * 8 + ji;
        float4 v;
        v.x = my_tanh(acc[ji][0]); v.y = my_tanh(acc[ji][1]);
        v.z = my_tanh(acc[ji][2]); v.w = my_tanh(acc[ji][3]);
        *(float4*)(sX + j * 128 + g) = v;
    }
}

__global__ __launch_bounds__(256, 3) void pair_kernel(
    const float* __restrict__ aw1, const float* __restrict__ ab1,
    const float* __restrict__ aw2, const float* __restrict__ ab2,
    const float* __restrict__ aw3, const float* __restrict__ ab3,
    const float* __restrict__ ab0, const int* __restrict__ dimp) {
    extern __shared__ __align__(16) char smem_raw[];
    PairSmem* sm = (PairSmem*)smem_raw;
    int dim = read_dim(dimp);
    int p0 = blockIdx.x * BLKP;
    if (p0 >= dim) return;               // uniform block exit
    int b = blockIdx.y, t = threadIdx.x;

    // ---- stage weights/biases into shared (split-half layout) ----
    {
        const float4* a1v = (const float4*)aw1;
        const float4* a2v = (const float4*)aw2;
#pragma unroll
        for (int it = 0; it < 4; ++it) {
            int g = t + 256 * it;
            int k = g >> 4, gg = g & 15;
            int half = gg & 1, j8 = gg >> 1;
            int di = k * 8 + j8;
            float4 v1 = a1v[g];
            float4 v2 = a2v[g];
            ((float4*)(half ? sm->Wb1 : sm->Wa1))[di] = v1;
            ((float4*)(half ? sm->Wb2 : sm->Wa2))[di] = v2;
        }
        if (t < 64) {
            sm->b1[t] = ab1[t];
            sm->b2[t] = ab2[t];
            sm->b0[t] = ab0[t];
            sm->Gg[t] = d_Gg[b * 64 + t];
            sm->W3[2 * t + 0] = aw3[2 * t + 0];
            sm->W3[2 * t + 1] = aw3[2 * t + 1];
        }
        if (t < 2) sm->b3[t] = ab3[t];
    }
    __syncthreads();

    // shift SA = sum_k |W3[k][0]|  (logit part <= SA since |h| < 1)
    float SA = 0.f;
#pragma unroll
    for (int k = 0; k < 64; ++k) SA += fabsf(sm->W3[2 * k]);

    // ---- layer 0: 2 threads per pair, each builds 32 features ----
    {
        int lp = t >> 1, half = t & 1;
        int p = p0 + lp;
        int cnt = d_count[b];
        int kb = half * 32;
        if (p < cnt && p < dim) {
            int q = d_order[b * DIMMAX + p];
            int i1 = q / Nn, i2 = q - i1 * Nn;
            const float4* Ga = (const float4*)(d_A + ((size_t)(b * Nn + i1)) * 64 + kb);
            const float4* Cc = (const float4*)(d_C + ((size_t)(b * Nn + i2)) * 64 + kb);
#pragma unroll
            for (int kk = 0; kk < 8; ++kk) {
                float4 a = Ga[kk], c = Cc[kk];
                int k = kb + 4 * kk;
                sm->X[xaddr(k + 0, lp)] = my_tanh(sm->Gg[k + 0] + a.x + c.x);
                sm->X[xaddr(k + 1, lp)] = my_tanh(sm->Gg[k + 1] + a.y + c.y);
                sm->X[xaddr(k + 2, lp)] = my_tanh(sm->Gg[k + 2] + a.z + c.z);
                sm->X[xaddr(k + 3, lp)] = my_tanh(sm->Gg[k + 3] + a.w + c.w);
            }
        } else {
            // invalid / out-of-range: zeroed input -> pre-activation = b0
#pragma unroll
            for (int k = kb; k < kb + 32; ++k) sm->X[xaddr(k, lp)] = my_tanh(sm->b0[k]);
        }
    }
    __syncthreads();

    int jg = t & 7, pg = t >> 3;
    float acc[8][4];

    // ---- layer 1 ----
    gemm64s(sm->X, sm->Wa1, sm->Wb1, sm->b1, acc, jg, pg);
    __syncthreads();
    tanh_store(sm->X, acc, jg, pg);
    __syncthreads();

    // ---- layer 2 ----
    gemm64s(sm->X, sm->Wa2, sm->Wb2, sm->b2, acc, jg, pg);
    __syncthreads();
    tanh_store(sm->X, acc, jg, pg);
    __syncthreads();

    // ---- layer 3: 2 threads per pair, shfl-combined (64 -> 2) ----
    {
        int lp = t >> 1, half = t & 1;
        int p = p0 + lp;
        float lg = 0.f, bl = 0.f;
        int kb = half * 32;
#pragma unroll
        for (int kk = 0; kk < 32; ++kk) {
            int k = kb + kk;
            float h = sm->X[xaddr(k, lp)];
            lg += h * sm->W3[2 * k + 0];
            bl += h * sm->W3[2 * k + 1];
        }
        lg += __shfl_xor_sync(0xffffffffu, lg, 1);
        bl += __shfl_xor_sync(0xffffffffu, bl, 1);
        if (half == 0 && p < dim) {
            // e = exp(logit - (b3 + SA)); softmax is shift-invariant
            d_logit[b * DIMMAX + p] = __expf(lg - SA);
            d_sig[b * DIMMAX + p] = 1.0f / (1.0f + __expf(-(bl + sm->b3[1])));
        }
    }
}

// ---------------- kernel 3: zero + sum(e) + scatter (one block per batch) -------
__global__ void softscatter_kernel(float* __restrict__ out, const int* __restrict__ dimp) {
    int b = blockIdx.x, t = threadIdx.x;  // 1024 threads
    int dim = read_dim(dimp);
    __shared__ float red[32];
    __shared__ float sInv;
    float* ob = out + (size_t)b * 20000;
    // zero this batch's output slab
    float4 z4 = make_float4(0.f, 0.f, 0.f, 0.f);
    for (int i = t; i < 5000; i += 1024) ((float4*)ob)[i] = z4;
    // sum of e
    float s = 0.f;
    for (int p = t; p < dim; p += 1024) s += d_logit[b * DIMMAX + p];
#pragma unroll
    for (int o = 16; o; o >>= 1) s += __shfl_xor_sync(0xffffffffu, s, o);
    if ((t & 31) == 0) red[t >> 5] = s;
    __syncthreads();
    if (t == 0) {
        float tot = 0.f;
        for (int i = 0; i < 32; ++i) tot += red[i];
        sInv = 1.0f / tot;
    }
    __syncthreads();
    float inv = sInv;
    int cnt = d_count[b];
    int lim = (cnt < dim) ? cnt : dim;
    for (int p = t; p < lim; p += 1024) {
        int q = d_order[b * DIMMAX + p];
        float pi = d_logit[b * DIMMAX + p] * inv;
        float sg = d_sig[b * DIMMAX + p];
        ob[q] = pi * sg;
        ob[10000 + q] = pi * (1.0f - sg);
    }
}

// ---------------- launcher (3 launches, single stream) ----------------
extern "C" void kernel_launch(void* const* d_in, const int* in_sizes, int n_in,
                              void* d_out, int out_size) {
    const float* emb = (const float*)d_in[0];
    const int* dimp;
    int base;
    if (n_in >= 18 && in_sizes[1] == 1) {   // dict order: emb, dim, actor..., critic...
        dimp = (const int*)d_in[1];
        base = 2;
    } else {                                // signature order: emb, actor..., critic..., dim
        dimp = (const int*)d_in[n_in - 1];
        base = 1;
    }
    const float* aw0 = (const float*)d_in[base + 0];
    const float* ab0 = (const float*)d_in[base + 1];
    const float* aw1 = (const float*)d_in[base + 2];
    const float* ab1 = (const float*)d_in[base + 3];
    const float* aw2 = (const float*)d_in[base + 4];
    const float* ab2 = (const float*)d_in[base + 5];
    const float* aw3 = (const float*)d_in[base + 6];
    const float* ab3 = (const float*)d_in[base + 7];
    const float* cw0 = (const float*)d_in[base + 8];
    const float* cb0 = (const float*)d_in[base + 9];
    const float* cw1 = (const float*)d_in[base + 10];
    const float* cb1 = (const float*)d_in[base + 11];
    const float* cw2 = (const float*)d_in[base + 12];
    const float* cb2 = (const float*)d_in[base + 13];
    const float* cw3 = (const float*)d_in[base + 14];
    const float* cb3 = (const float*)d_in[base + 15];

    float* out = (float*)d_out;
    int voff = out_size - Bz;  // value slot after the filled region (expect 640000)

    static int init_done = 0;
    if (!init_done) {
        cudaFuncSetAttribute(pair_kernel, cudaFuncAttributeMaxDynamicSharedMemorySize,
                             PAIR_SMEM_BYTES);
        init_done = 1;
    }

    prep_kernel<<<dim3(Bz, 7), 256, PREP_SMEM>>>(emb, aw0, ab0, cw0, cb0, cw1, cb1,
                                                 cw2, cb2, cw3, cb3, out, voff, dimp);
    pair_kernel<<<dim3(PBLK, Bz), 256, PAIR_SMEM_BYTES>>>(aw1, ab1, aw2, ab2, aw3, ab3,
                                                          ab0, dimp);
    softscatter_kernel<<<Bz, 1024>>>(out, dimp);
}